// round 13
// baseline (speedup 1.0000x reference)
#include <cuda_runtime.h>
#include <math.h>

#define H 1024
#define V 50257
#define L 4096
#define NPART 512                   // ctx_part blocks (8 enc rows each)
#define NRED 64                     // reducer blocks inside ctx_part
#define NT 3142                     // logits blocks (16 rows each)
#define FIN_BLOCKS ((V + 255) / 256)   // 197
#define NEG_BIG (-3.0e38f)

// ---------------- device scratch (no allocations allowed) ----------------
__device__ float g_concat[2 * H];            // [0..H) = ctx, [H..2H) = h_new
__device__ float4 g_ctx_part4[NPART * 256];  // 512 partials x 1024 cols (float4) = 2 MB
__device__ float g_scores[L];
__device__ float g_spart[2 * NPART];         // per-block (max, sumexp) for attn softmax
__device__ float g_part[2 * NT];             // per-logits-block (max, sumexp)
__device__ int   g_ctx_done;

// ---------------- helpers ----------------
__device__ __forceinline__ float warp_sum(float v) {
#pragma unroll
    for (int o = 16; o > 0; o >>= 1) v += __shfl_down_sync(0xFFFFFFFFu, v, o);
    return v;
}
__device__ __forceinline__ float dot4(const float4 a, const float4 b) {
    return a.x * b.x + a.y * b.y + a.z * b.z + a.w * b.w;
}

// ---------------- 1) GRU cell: one block per output element j ----------------
__global__ void __launch_bounds__(128) gru_kernel(
    const int* __restrict__ inp, const float* __restrict__ hidden,
    const float* __restrict__ embedding,
    const float* __restrict__ w_ih, const float* __restrict__ w_hh,
    const float* __restrict__ b_ih, const float* __restrict__ b_hh,
    float* __restrict__ out_h)
{
    __shared__ float4 xs[H / 4];
    __shared__ float4 hs[H / 4];
    __shared__ float red[6][4];
    const int j = blockIdx.x;
    const int tid = threadIdx.x;
    const int idx = inp[0];   // low 32 bits of the (int64) token id — LE safe

    if (j == 0 && tid == 0) g_ctx_done = 0;   // reset fusion counter for this replay

    const float4* emb4 = (const float4*)(embedding + (size_t)idx * H);
    const float4* hid4 = (const float4*)hidden;
    xs[tid]       = emb4[tid];        xs[tid + 128] = emb4[tid + 128];
    hs[tid]       = hid4[tid];        hs[tid + 128] = hid4[tid + 128];
    __syncthreads();

    const float4* wi0 = (const float4*)(w_ih + (size_t)j * H);
    const float4* wi1 = (const float4*)(w_ih + (size_t)(j + H) * H);
    const float4* wi2 = (const float4*)(w_ih + (size_t)(j + 2 * H) * H);
    const float4* wh0 = (const float4*)(w_hh + (size_t)j * H);
    const float4* wh1 = (const float4*)(w_hh + (size_t)(j + H) * H);
    const float4* wh2 = (const float4*)(w_hh + (size_t)(j + 2 * H) * H);

    float a0 = 0.f, a1 = 0.f, a2 = 0.f, a3 = 0.f, a4 = 0.f, a5 = 0.f;
#pragma unroll
    for (int p = 0; p < 2; p++) {
        const int k = tid + 128 * p;
        const float4 xv = xs[k], hv = hs[k];
        float4 w;
        w = wi0[k]; a0 += dot4(w, xv);
        w = wi1[k]; a1 += dot4(w, xv);
        w = wi2[k]; a2 += dot4(w, xv);
        w = wh0[k]; a3 += dot4(w, hv);
        w = wh1[k]; a4 += dot4(w, hv);
        w = wh2[k]; a5 += dot4(w, hv);
    }
#if __CUDA_ARCH__ >= 900
    cudaTriggerProgrammaticLaunchCompletion();   // let scores' blocks launch + prefetch enc
#endif
    a0 = warp_sum(a0); a1 = warp_sum(a1); a2 = warp_sum(a2);
    a3 = warp_sum(a3); a4 = warp_sum(a4); a5 = warp_sum(a5);
    const int warp = tid >> 5, lane = tid & 31;
    if (lane == 0) {
        red[0][warp] = a0; red[1][warp] = a1; red[2][warp] = a2;
        red[3][warp] = a3; red[4][warp] = a4; red[5][warp] = a5;
    }
    __syncthreads();
    if (tid == 0) {
        float s[6];
#pragma unroll
        for (int q = 0; q < 6; q++) s[q] = red[q][0] + red[q][1] + red[q][2] + red[q][3];
        const float i_r = s[0] + b_ih[j];
        const float i_z = s[1] + b_ih[j + H];
        const float i_n = s[2] + b_ih[j + 2 * H];
        const float h_r = s[3] + b_hh[j];
        const float h_z = s[4] + b_hh[j + H];
        const float h_n = s[5] + b_hh[j + 2 * H];
        const float r = 1.f / (1.f + __expf(-(i_r + h_r)));
        const float z = 1.f / (1.f + __expf(-(i_z + h_z)));
        const float n = tanhf(i_n + r * h_n);
        const float hj = ((const float*)hs)[j];
        const float hv = (1.f - z) * n + z * hj;
        g_concat[H + j] = hv;     // h_new half of concat
        out_h[j]        = hv;     // second output tensor
    }
}

// ---------------- 2) scores: prefetch enc into regs BEFORE the dependency wait --------
__global__ void __launch_bounds__(256) scores_kernel(const float* __restrict__ enc)
{
    __shared__ float4 hshr[H / 4];
    __shared__ float sarr[8];
    const int tid = threadIdx.x;
    const int warp = tid >> 5, lane = tid & 31;
    const int row = blockIdx.x * 8 + warp;      // grid = L/8 = 512
    const float4* er = (const float4*)(enc + (size_t)row * H);
    float4 rv[8];
#pragma unroll
    for (int i = 0; i < 8; i++) rv[i] = er[lane + 32 * i];   // independent of gru
#if __CUDA_ARCH__ >= 900
    cudaGridDependencySynchronize();             // wait for gru before touching h_new
#endif
    const float4* hc = (const float4*)(&g_concat[H]);
    hshr[tid] = hc[tid];
    __syncthreads();
    float acc = 0.f;
#pragma unroll
    for (int i = 0; i < 8; i++) acc += dot4(rv[i], hshr[lane + 32 * i]);
    acc = warp_sum(acc);
    if (lane == 0) { g_scores[row] = acc; sarr[warp] = acc; }
    __syncthreads();
    if (tid == 0) {
        float m = sarr[0];
#pragma unroll
        for (int k = 1; k < 8; k++) m = fmaxf(m, sarr[k]);
        float s = 0.f;
#pragma unroll
        for (int k = 0; k < 8; k++) s += __expf(sarr[k] - m);
        g_spart[2 * blockIdx.x]     = m;
        g_spart[2 * blockIdx.x + 1] = s;
    }
}

// ---- 3) ctx: partials + FUSED reduction (blocks 0..63 spin, all blocks co-resident) ----
__global__ void __launch_bounds__(256) ctx_part_kernel(const float* __restrict__ enc)
{
    __shared__ float sm[8], ss[8];
    __shared__ float wts[8];
    const int tid = threadIdx.x;
    const int warp = tid >> 5, lane = tid & 31;
    const int l0 = blockIdx.x * 8;           // grid = NPART = 512
#if __CUDA_ARCH__ >= 900
    cudaGridDependencySynchronize();         // wait for scores
#endif

    // ---- merge the 512 (max,sumexp) pairs: 2 per thread, then tree ----
    float m = g_spart[2 * tid], s = g_spart[2 * tid + 1];
    {
        const float m2 = g_spart[2 * (tid + 256)], s2 = g_spart[2 * (tid + 256) + 1];
        const float nm = fmaxf(m, m2);
        s = s * __expf(m - nm) + s2 * __expf(m2 - nm);
        m = nm;
    }
#pragma unroll
    for (int o = 16; o > 0; o >>= 1) {
        const float om = __shfl_down_sync(0xFFFFFFFFu, m, o);
        const float os = __shfl_down_sync(0xFFFFFFFFu, s, o);
        const float nm = fmaxf(m, om);
        s = s * __expf(m - nm) + os * __expf(om - nm);
        m = nm;
    }
    if (lane == 0) { sm[warp] = m; ss[warp] = s; }
    __syncthreads();
    if (tid < 8) {
        float M = sm[0], S = ss[0];
#pragma unroll
        for (int k = 1; k < 8; k++) {
            const float nm = fmaxf(M, sm[k]);
            S = S * __expf(M - nm) + ss[k] * __expf(sm[k] - nm);
            M = nm;
        }
        wts[tid] = __expf(g_scores[l0 + tid] - M) / S;   // this block's 8 attn weights
    }
    __syncthreads();

    // ---- weighted row accumulation: 8 independent float4 loads (enc L2-hot) ----
    const float4* e4 = (const float4*)enc;
    float4 acc = make_float4(0.f, 0.f, 0.f, 0.f);
#pragma unroll
    for (int l = 0; l < 8; l++) {
        const float a = wts[l];
        const float4 v = e4[(size_t)(l0 + l) * 256 + tid];
        acc.x += a * v.x; acc.y += a * v.y; acc.z += a * v.z; acc.w += a * v.w;
    }
    g_ctx_part4[blockIdx.x * 256 + tid] = acc;
    __threadfence();
    __syncthreads();
    if (tid == 0) atomicAdd(&g_ctx_done, 1);

    // ---- blocks 0..63: wait for all partials, then reduce ----
    if (blockIdx.x < NRED) {
        if (tid == 0) { while (atomicAdd(&g_ctx_done, 0) < NPART) { } }
        __syncthreads();
        __threadfence();
        __shared__ float4 sred[256];
        const int b  = blockIdx.x;
        const int c4 = tid & 3;
        const int pg = tid >> 2;
        float4 racc = make_float4(0.f, 0.f, 0.f, 0.f);
#pragma unroll
        for (int k = 0; k < NPART / 64; k++) {
            const float4 v = g_ctx_part4[(pg + 64 * k) * 256 + b * 4 + c4];
            racc.x += v.x; racc.y += v.y; racc.z += v.z; racc.w += v.w;
        }
        sred[tid] = racc;
        __syncthreads();
#pragma unroll
        for (int off = 32; off >= 1; off >>= 1) {
            if (pg < off) {
                const float4 v = sred[tid + off * 4];
                float4 t = sred[tid];
                t.x += v.x; t.y += v.y; t.z += v.z; t.w += v.w;
                sred[tid] = t;
            }
            __syncthreads();
        }
        if (pg == 0) ((float4*)g_concat)[b * 4 + c4] = sred[tid];
    }
}

// ---- 4) logits: warp-per-row matvec + one-time per-block LSE partial tail ----
__global__ void __launch_bounds__(512) logits_kernel(
    const float* __restrict__ out_w, const float* __restrict__ out_b,
    float* __restrict__ logits)
{
    __shared__ float4 cs[512];          // concat (2048 floats) as float4
    __shared__ float arr[16];
    const int tid = threadIdx.x;
#if __CUDA_ARCH__ >= 900
    cudaGridDependencySynchronize();    // wait for ctx_part
#endif
    const float4* cc = (const float4*)g_concat;
    cs[tid] = cc[tid];
    __syncthreads();
    const int warp = tid >> 5, lane = tid & 31;
    const int row = blockIdx.x * 16 + warp;
    float lgv = NEG_BIG;
    if (row < V) {
        const float4* wr = (const float4*)(out_w + (size_t)row * (2 * H));
        float acc = 0.f;
#pragma unroll
        for (int i = 0; i < 16; i++) {
            const float4 w4 = __ldcs(&wr[lane + 32 * i]);   // streaming: don't pollute L2
            const float4 c4 = cs[lane + 32 * i];
            acc += dot4(w4, c4);
        }
        acc = warp_sum(acc);
        if (lane == 0) {
            lgv = acc + out_b[row];
            logits[row] = lgv;
        }
    }
    // ---- one-time tail: per-block (max, sumexp) from registers ----
    if (lane == 0) arr[warp] = lgv;
    __syncthreads();
    if (tid == 0) {
        float m = arr[0];
#pragma unroll
        for (int k = 1; k < 16; k++) m = fmaxf(m, arr[k]);
        float s = 0.f;
#pragma unroll
        for (int k = 0; k < 16; k++) s += __expf(arr[k] - m);   // NEG_BIG -> 0
        g_part[2 * blockIdx.x]     = m;
        g_part[2 * blockIdx.x + 1] = s;
    }
}

// ---- 5) finalize: SPIN-FREE — redundant fixed-order merge of 3142 pairs, subtract ----
__global__ void __launch_bounds__(256) finalize_kernel(float* __restrict__ logits)
{
    __shared__ float sm[8], ss[8];
    __shared__ float lse_s;
    const int tid = threadIdx.x;
    const int warp = tid >> 5, lane = tid & 31;
#if __CUDA_ARCH__ >= 900
    cudaGridDependencySynchronize();    // logits complete -> all g_part visible
#endif
    // thread t merges pairs t, t+256, ... in fixed order (deterministic)
    float m = NEG_BIG, s = 0.f;
    for (int p = tid; p < NT; p += 256) {
        const float pm = g_part[2 * p], ps = g_part[2 * p + 1];
        const float nm = fmaxf(m, pm);
        s = s * __expf(m - nm) + ps * __expf(pm - nm);
        m = nm;
    }
#pragma unroll
    for (int o = 16; o > 0; o >>= 1) {
        const float om = __shfl_down_sync(0xFFFFFFFFu, m, o);
        const float os = __shfl_down_sync(0xFFFFFFFFu, s, o);
        const float nm = fmaxf(m, om);
        s = s * __expf(m - nm) + os * __expf(om - nm);
        m = nm;
    }
    if (lane == 0) { sm[warp] = m; ss[warp] = s; }
    __syncthreads();
    if (tid == 0) {
        float M = sm[0], S = ss[0];
#pragma unroll
        for (int k = 1; k < 8; k++) {
            const float nm = fmaxf(M, sm[k]);
            S = S * __expf(M - nm) + ss[k] * __expf(sm[k] - nm);
            M = nm;
        }
        lse_s = M + logf(S);
    }
    __syncthreads();
    const int v = blockIdx.x * 256 + tid;
    if (v < V) logits[v] -= lse_s;
}

// ---------------- launcher (PDL on the 4 dependent edges) ----------------
static void launch_pdl(void* fn, dim3 grid, dim3 block, void** args)
{
    cudaLaunchConfig_t cfg = {};
    cfg.gridDim = grid;
    cfg.blockDim = block;
    cudaLaunchAttribute attr[1];
    attr[0].id = cudaLaunchAttributeProgrammaticStreamSerialization;
    attr[0].val.programmaticStreamSerializationAllowed = 1;
    cfg.attrs = attr;
    cfg.numAttrs = 1;
    cudaLaunchKernelExC(&cfg, fn, args);
}

extern "C" void kernel_launch(void* const* d_in, const int* in_sizes, int n_in,
                              void* d_out, int out_size)
{
    const int*   inp   = (const int*)  d_in[0];   // token id (read low 32 bits)
    const float* hidden= (const float*)d_in[1];
    const float* enc   = (const float*)d_in[2];
    const float* emb   = (const float*)d_in[3];
    const float* w_ih  = (const float*)d_in[4];
    const float* w_hh  = (const float*)d_in[5];
    const float* b_ih  = (const float*)d_in[6];
    const float* b_hh  = (const float*)d_in[7];
    const float* out_w = (const float*)d_in[8];
    const float* out_b = (const float*)d_in[9];
    float* out = (float*)d_out;                   // [0..V) log-probs, [V..V+H) h_new
    float* out_h = out + V;

    gru_kernel<<<H, 128>>>(inp, hidden, emb, w_ih, w_hh, b_ih, b_hh, out_h);

    {   // scores (PDL: launches during gru tail, prefetches enc)
        void* args[] = { (void*)&enc };
        launch_pdl((void*)scores_kernel, dim3(L / 8), dim3(256), args);
    }
    {   // ctx_part (PDL)
        void* args[] = { (void*)&enc };
        launch_pdl((void*)ctx_part_kernel, dim3(NPART), dim3(256), args);
    }
    {   // logits (PDL)
        void* args[] = { (void*)&out_w, (void*)&out_b, (void*)&out };
        launch_pdl((void*)logits_kernel, dim3(NT), dim3(512), args);
    }
    {   // finalize (PDL, spin-free)
        void* args[] = { (void*)&out };
        launch_pdl((void*)finalize_kernel, dim3(FIN_BLOCKS), dim3(256), args);
    }
}

// round 14
// speedup vs baseline: 1.1342x; 1.1342x over previous
#include <cuda_runtime.h>
#include <math.h>

#define H 1024
#define V 50257
#define L 4096
#define NPART 512                   // ctx_part blocks (8 enc rows each)
#define NRED 64                     // reducer blocks inside ctx_part
#define FIN_BLOCKS ((V + 255) / 256)   // 197
#define NEG_BIG (-3.0e38f)

// ---------------- device scratch (no allocations allowed) ----------------
__device__ float g_concat[2 * H];            // [0..H) = ctx, [H..2H) = h_new
__device__ float4 g_ctx_part4[NPART * 256];  // 512 partials x 1024 cols (float4) = 2 MB
__device__ float g_scores[L];
__device__ float g_spart[2 * NPART];         // per-block (max, sumexp) for attn softmax
__device__ float g_part[2 * FIN_BLOCKS];     // per-block (max, sumexp) for logit LSE
__device__ int   g_ctx_done;
__device__ int   g_lse_done;

// ---------------- helpers ----------------
__device__ __forceinline__ float warp_sum(float v) {
#pragma unroll
    for (int o = 16; o > 0; o >>= 1) v += __shfl_down_sync(0xFFFFFFFFu, v, o);
    return v;
}
__device__ __forceinline__ float dot4(const float4 a, const float4 b) {
    return a.x * b.x + a.y * b.y + a.z * b.z + a.w * b.w;
}

// ---------------- 1) GRU cell: one block per output element j ----------------
__global__ void __launch_bounds__(128) gru_kernel(
    const int* __restrict__ inp, const float* __restrict__ hidden,
    const float* __restrict__ embedding,
    const float* __restrict__ w_ih, const float* __restrict__ w_hh,
    const float* __restrict__ b_ih, const float* __restrict__ b_hh,
    float* __restrict__ out_h)
{
    __shared__ float4 xs[H / 4];
    __shared__ float4 hs[H / 4];
    __shared__ float red[6][4];
    const int j = blockIdx.x;
    const int tid = threadIdx.x;
    const int idx = inp[0];   // low 32 bits of the (int64) token id — LE safe

    if (j == 0 && tid == 0) { g_ctx_done = 0; g_lse_done = 0; }   // reset fusion counters

    const float4* emb4 = (const float4*)(embedding + (size_t)idx * H);
    const float4* hid4 = (const float4*)hidden;
    xs[tid]       = emb4[tid];        xs[tid + 128] = emb4[tid + 128];
    hs[tid]       = hid4[tid];        hs[tid + 128] = hid4[tid + 128];
    __syncthreads();

    const float4* wi0 = (const float4*)(w_ih + (size_t)j * H);
    const float4* wi1 = (const float4*)(w_ih + (size_t)(j + H) * H);
    const float4* wi2 = (const float4*)(w_ih + (size_t)(j + 2 * H) * H);
    const float4* wh0 = (const float4*)(w_hh + (size_t)j * H);
    const float4* wh1 = (const float4*)(w_hh + (size_t)(j + H) * H);
    const float4* wh2 = (const float4*)(w_hh + (size_t)(j + 2 * H) * H);

    float a0 = 0.f, a1 = 0.f, a2 = 0.f, a3 = 0.f, a4 = 0.f, a5 = 0.f;
#pragma unroll
    for (int p = 0; p < 2; p++) {
        const int k = tid + 128 * p;
        const float4 xv = xs[k], hv = hs[k];
        float4 w;
        w = wi0[k]; a0 += dot4(w, xv);
        w = wi1[k]; a1 += dot4(w, xv);
        w = wi2[k]; a2 += dot4(w, xv);
        w = wh0[k]; a3 += dot4(w, hv);
        w = wh1[k]; a4 += dot4(w, hv);
        w = wh2[k]; a5 += dot4(w, hv);
    }
#if __CUDA_ARCH__ >= 900
    cudaTriggerProgrammaticLaunchCompletion();   // let scores' blocks launch + prefetch enc
#endif
    a0 = warp_sum(a0); a1 = warp_sum(a1); a2 = warp_sum(a2);
    a3 = warp_sum(a3); a4 = warp_sum(a4); a5 = warp_sum(a5);
    const int warp = tid >> 5, lane = tid & 31;
    if (lane == 0) {
        red[0][warp] = a0; red[1][warp] = a1; red[2][warp] = a2;
        red[3][warp] = a3; red[4][warp] = a4; red[5][warp] = a5;
    }
    __syncthreads();
    if (tid == 0) {
        float s[6];
#pragma unroll
        for (int q = 0; q < 6; q++) s[q] = red[q][0] + red[q][1] + red[q][2] + red[q][3];
        const float i_r = s[0] + b_ih[j];
        const float i_z = s[1] + b_ih[j + H];
        const float i_n = s[2] + b_ih[j + 2 * H];
        const float h_r = s[3] + b_hh[j];
        const float h_z = s[4] + b_hh[j + H];
        const float h_n = s[5] + b_hh[j + 2 * H];
        const float r = 1.f / (1.f + __expf(-(i_r + h_r)));
        const float z = 1.f / (1.f + __expf(-(i_z + h_z)));
        const float n = tanhf(i_n + r * h_n);
        const float hj = ((const float*)hs)[j];
        const float hv = (1.f - z) * n + z * hj;
        g_concat[H + j] = hv;     // h_new half of concat
        out_h[j]        = hv;     // second output tensor
    }
}

// ---------------- 2) scores: prefetch enc into regs BEFORE the dependency wait --------
__global__ void __launch_bounds__(256) scores_kernel(const float* __restrict__ enc)
{
    __shared__ float4 hshr[H / 4];
    __shared__ float sarr[8];
    const int tid = threadIdx.x;
    const int warp = tid >> 5, lane = tid & 31;
    const int row = blockIdx.x * 8 + warp;      // grid = L/8 = 512
    const float4* er = (const float4*)(enc + (size_t)row * H);
    float4 rv[8];
#pragma unroll
    for (int i = 0; i < 8; i++) rv[i] = er[lane + 32 * i];   // independent of gru
#if __CUDA_ARCH__ >= 900
    cudaGridDependencySynchronize();             // wait for gru before touching h_new
#endif
    const float4* hc = (const float4*)(&g_concat[H]);
    hshr[tid] = hc[tid];
    __syncthreads();
    float acc = 0.f;
#pragma unroll
    for (int i = 0; i < 8; i++) acc += dot4(rv[i], hshr[lane + 32 * i]);
    acc = warp_sum(acc);
    if (lane == 0) { g_scores[row] = acc; sarr[warp] = acc; }
    __syncthreads();
    if (tid == 0) {
        float m = sarr[0];
#pragma unroll
        for (int k = 1; k < 8; k++) m = fmaxf(m, sarr[k]);
        float s = 0.f;
#pragma unroll
        for (int k = 0; k < 8; k++) s += __expf(sarr[k] - m);
        g_spart[2 * blockIdx.x]     = m;
        g_spart[2 * blockIdx.x + 1] = s;
    }
}

// ---- 3) ctx: partials + FUSED reduction (blocks 0..63 spin, all blocks co-resident) ----
__global__ void __launch_bounds__(256) ctx_part_kernel(const float* __restrict__ enc)
{
    __shared__ float sm[8], ss[8];
    __shared__ float wts[8];
    const int tid = threadIdx.x;
    const int warp = tid >> 5, lane = tid & 31;
    const int l0 = blockIdx.x * 8;           // grid = NPART = 512
#if __CUDA_ARCH__ >= 900
    cudaGridDependencySynchronize();         // wait for scores
#endif

    // ---- merge the 512 (max,sumexp) pairs: 2 per thread, then tree ----
    float m = g_spart[2 * tid], s = g_spart[2 * tid + 1];
    {
        const float m2 = g_spart[2 * (tid + 256)], s2 = g_spart[2 * (tid + 256) + 1];
        const float nm = fmaxf(m, m2);
        s = s * __expf(m - nm) + s2 * __expf(m2 - nm);
        m = nm;
    }
#pragma unroll
    for (int o = 16; o > 0; o >>= 1) {
        const float om = __shfl_down_sync(0xFFFFFFFFu, m, o);
        const float os = __shfl_down_sync(0xFFFFFFFFu, s, o);
        const float nm = fmaxf(m, om);
        s = s * __expf(m - nm) + os * __expf(om - nm);
        m = nm;
    }
    if (lane == 0) { sm[warp] = m; ss[warp] = s; }
    __syncthreads();
    if (tid < 8) {
        float M = sm[0], S = ss[0];
#pragma unroll
        for (int k = 1; k < 8; k++) {
            const float nm = fmaxf(M, sm[k]);
            S = S * __expf(M - nm) + ss[k] * __expf(sm[k] - nm);
            M = nm;
        }
        wts[tid] = __expf(g_scores[l0 + tid] - M) / S;   // this block's 8 attn weights
    }
    __syncthreads();

    // ---- weighted row accumulation: 8 independent float4 loads (enc L2-hot) ----
    const float4* e4 = (const float4*)enc;
    float4 acc = make_float4(0.f, 0.f, 0.f, 0.f);
#pragma unroll
    for (int l = 0; l < 8; l++) {
        const float a = wts[l];
        const float4 v = e4[(size_t)(l0 + l) * 256 + tid];
        acc.x += a * v.x; acc.y += a * v.y; acc.z += a * v.z; acc.w += a * v.w;
    }
    g_ctx_part4[blockIdx.x * 256 + tid] = acc;
    __threadfence();
    __syncthreads();
    if (tid == 0) atomicAdd(&g_ctx_done, 1);

    // ---- blocks 0..63: wait for all partials, then reduce ----
    if (blockIdx.x < NRED) {
        if (tid == 0) { while (atomicAdd(&g_ctx_done, 0) < NPART) { } }
        __syncthreads();
        __threadfence();
        __shared__ float4 sred[256];
        const int b  = blockIdx.x;
        const int c4 = tid & 3;
        const int pg = tid >> 2;
        float4 racc = make_float4(0.f, 0.f, 0.f, 0.f);
#pragma unroll
        for (int k = 0; k < NPART / 64; k++) {
            const float4 v = g_ctx_part4[(pg + 64 * k) * 256 + b * 4 + c4];
            racc.x += v.x; racc.y += v.y; racc.z += v.z; racc.w += v.w;
        }
        sred[tid] = racc;
        __syncthreads();
#pragma unroll
        for (int off = 32; off >= 1; off >>= 1) {
            if (pg < off) {
                const float4 v = sred[tid + off * 4];
                float4 t = sred[tid];
                t.x += v.x; t.y += v.y; t.z += v.z; t.w += v.w;
                sred[tid] = t;
            }
            __syncthreads();
        }
        if (pg == 0) ((float4*)g_concat)[b * 4 + c4] = sred[tid];
    }
}

// ---------------- 4) logits: warp-per-row float4 matvec (R7/R11 shape) ----------------
__global__ void __launch_bounds__(512) logits_kernel(
    const float* __restrict__ out_w, const float* __restrict__ out_b,
    float* __restrict__ logits)
{
    __shared__ float4 cs[512];          // concat (2048 floats) as float4
    const int tid = threadIdx.x;
#if __CUDA_ARCH__ >= 900
    cudaGridDependencySynchronize();    // wait for ctx_part
#endif
    const float4* cc = (const float4*)g_concat;
    cs[tid] = cc[tid];
    __syncthreads();
    const int warp = tid >> 5, lane = tid & 31;
    const int row = blockIdx.x * 16 + warp;
    if (row >= V) return;
    const float4* wr = (const float4*)(out_w + (size_t)row * (2 * H));
    float acc = 0.f;
#pragma unroll
    for (int i = 0; i < 16; i++) {
        const float4 w4 = __ldcs(&wr[lane + 32 * i]);   // streaming: don't pollute L2
        const float4 c4 = cs[lane + 32 * i];
        acc += dot4(w4, c4);
    }
    acc = warp_sum(acc);
    if (lane == 0) logits[row] = acc + out_b[row];
}

// ---- 5) finalize: per-block LSE partial + spin + redundant merge + subtract ----
__global__ void __launch_bounds__(256) finalize_kernel(float* __restrict__ logits)
{
    __shared__ float sm[8], ss[8];
    __shared__ float lse_s;
    const int tid = threadIdx.x;
    const int warp = tid >> 5, lane = tid & 31;
    const int v = blockIdx.x * 256 + tid;
#if __CUDA_ARCH__ >= 900
    cudaGridDependencySynchronize();    // wait for logits
#endif
    const float lg = (v < V) ? logits[v] : NEG_BIG;

    // block-local (max, sumexp)
    float m = lg;
#pragma unroll
    for (int o = 16; o > 0; o >>= 1) m = fmaxf(m, __shfl_down_sync(0xFFFFFFFFu, m, o));
    if (lane == 0) sm[warp] = m;
    __syncthreads();
    if (tid == 0) {
        float t = sm[0];
#pragma unroll
        for (int k = 1; k < 8; k++) t = fmaxf(t, sm[k]);
        lse_s = t;   // broadcast of block max
    }
    __syncthreads();
    const float bm = lse_s;
    float s = (v < V) ? __expf(lg - bm) : 0.f;
    s = warp_sum(s);
    if (lane == 0) ss[warp] = s;
    __syncthreads();
    if (tid == 0) {
        float t = ss[0];
#pragma unroll
        for (int k = 1; k < 8; k++) t += ss[k];
        g_part[2 * blockIdx.x]     = bm;
        g_part[2 * blockIdx.x + 1] = t;
        __threadfence();
        atomicAdd(&g_lse_done, 1);
        while (atomicAdd(&g_lse_done, 0) < FIN_BLOCKS) { }
    }
    __syncthreads();
    __threadfence();

    // redundant merge of all 197 pairs (L2-hot, fixed order -> deterministic)
    float mm = NEG_BIG, msum = 0.f;
    if (tid < FIN_BLOCKS) { mm = g_part[2 * tid]; msum = g_part[2 * tid + 1]; }
#pragma unroll
    for (int o = 16; o > 0; o >>= 1) {
        const float om = __shfl_down_sync(0xFFFFFFFFu, mm, o);
        const float os = __shfl_down_sync(0xFFFFFFFFu, msum, o);
        const float nm = fmaxf(mm, om);
        msum = msum * __expf(mm - nm) + os * __expf(om - nm);
        mm = nm;
    }
    if (lane == 0) { sm[warp] = mm; ss[warp] = msum; }
    __syncthreads();
    if (tid == 0) {
        float M = sm[0], S = ss[0];
#pragma unroll
        for (int k = 1; k < 8; k++) {
            const float nm = fmaxf(M, sm[k]);
            S = S * __expf(M - nm) + ss[k] * __expf(sm[k] - nm);
            M = nm;
        }
        lse_s = M + logf(S);
    }
    __syncthreads();
    if (v < V) logits[v] = lg - lse_s;
}

// ---------------- launcher (PDL on the 4 dependent edges) ----------------
static void launch_pdl(void* fn, dim3 grid, dim3 block, void** args)
{
    cudaLaunchConfig_t cfg = {};
    cfg.gridDim = grid;
    cfg.blockDim = block;
    cudaLaunchAttribute attr[1];
    attr[0].id = cudaLaunchAttributeProgrammaticStreamSerialization;
    attr[0].val.programmaticStreamSerializationAllowed = 1;
    cfg.attrs = attr;
    cfg.numAttrs = 1;
    cudaLaunchKernelExC(&cfg, fn, args);
}

extern "C" void kernel_launch(void* const* d_in, const int* in_sizes, int n_in,
                              void* d_out, int out_size)
{
    const int*   inp   = (const int*)  d_in[0];   // token id (read low 32 bits)
    const float* hidden= (const float*)d_in[1];
    const float* enc   = (const float*)d_in[2];
    const float* emb   = (const float*)d_in[3];
    const float* w_ih  = (const float*)d_in[4];
    const float* w_hh  = (const float*)d_in[5];
    const float* b_ih  = (const float*)d_in[6];
    const float* b_hh  = (const float*)d_in[7];
    const float* out_w = (const float*)d_in[8];
    const float* out_b = (const float*)d_in[9];
    float* out = (float*)d_out;                   // [0..V) log-probs, [V..V+H) h_new
    float* out_h = out + V;

    gru_kernel<<<H, 128>>>(inp, hidden, emb, w_ih, w_hh, b_ih, b_hh, out_h);

    {   // scores (PDL: launches during gru tail, prefetches enc)
        void* args[] = { (void*)&enc };
        launch_pdl((void*)scores_kernel, dim3(L / 8), dim3(256), args);
    }
    {   // ctx_part (PDL)
        void* args[] = { (void*)&enc };
        launch_pdl((void*)ctx_part_kernel, dim3(NPART), dim3(256), args);
    }
    {   // logits (PDL)
        void* args[] = { (void*)&out_w, (void*)&out_b, (void*)&out };
        launch_pdl((void*)logits_kernel, dim3((V + 15) / 16), dim3(512), args);
    }
    {   // finalize (PDL)
        void* args[] = { (void*)&out };
        launch_pdl((void*)finalize_kernel, dim3(FIN_BLOCKS), dim3(256), args);
    }
}